// round 17
// baseline (speedup 1.0000x reference)
#include <cuda_runtime.h>
#include <cuda_fp16.h>
#include <cstdint>

#define NN 50000
#define NE 800000
#define NG 512
#define GRID 148
#define THREADS 1024
#define NWARP (GRID * 32)

// ---------------- scratch ----------------
__device__ uint32_t g_agg16[(size_t)NN * 64]; // MEAN as fp16x2
__device__ uint32_t g_x16[(size_t)NN * 64];   // fp16x2 copy of x
__device__ uint32_t g_h116[(size_t)NN * 64];  // fp16x2 h1
__device__ float g_pool[NG * 128];
__device__ int g_src[NE];
__device__ int g_dst[NE];
__device__ int g_ssrc[NE];                  // src ids grouped by dst (CSR)
__device__ int g_deg[NN];
__device__ int g_off[NN + 1];
__device__ int g_cur[NN];
__device__ int g_bsum[256];
__device__ int g_bat[NN];
__device__ int g_eflag = 0;   // sticky, input-determined
__device__ int g_bflag = 0;
__device__ unsigned long long g_sync = 0;   // monotonic grid-sync counter

// ---------------- helpers ----------------
__device__ __forceinline__ uint32_t smem_u32(const void* p) {
    return (uint32_t)__cvta_generic_to_shared(p);
}

__device__ __forceinline__ uint32_t packf16(float a, float b) {
    __half2 h = __floats2half2_rn(a, b);
    return *(uint32_t*)&h;
}

__device__ __forceinline__ void mma16816(float* c, const uint32_t* a,
                                         uint32_t b0, uint32_t b1) {
    asm volatile(
        "mma.sync.aligned.m16n8k16.row.col.f32.f16.f16.f32 "
        "{%0,%1,%2,%3}, {%4,%5,%6,%7}, {%8,%9}, {%0,%1,%2,%3};"
        : "+f"(c[0]), "+f"(c[1]), "+f"(c[2]), "+f"(c[3])
        : "r"(a[0]), "r"(a[1]), "r"(a[2]), "r"(a[3]), "r"(b0), "r"(b1));
}

__device__ __forceinline__ void ldsm4(uint32_t* r, uint32_t addr) {
    asm volatile("ldmatrix.sync.aligned.m8n8.x4.shared.b16 {%0,%1,%2,%3}, [%4];"
                 : "=r"(r[0]), "=r"(r[1]), "=r"(r[2]), "=r"(r[3]) : "r"(addr));
}

__device__ __forceinline__ void h4acc(uint2 raw, float4& acc) {
    float2 f0 = __half22float2(*(__half2*)&raw.x);
    float2 f1 = __half22float2(*(__half2*)&raw.y);
    acc.x += f0.x; acc.y += f0.y; acc.z += f1.x; acc.w += f1.y;
}

// monotonic grid sync: works across graph replays because every launch
// performs a fixed number of syncs (counter stays a multiple of GRID).
__device__ __forceinline__ void gsync(int t) {
    __syncthreads();
    __threadfence();
    if (t == 0) {
        unsigned long long o = atomicAdd(&g_sync, 1ULL);
        unsigned long long target = (o / GRID + 1ULL) * GRID;
        while (*(volatile unsigned long long*)&g_sync < target) __nanosleep(32);
    }
    __syncthreads();
    __threadfence();
}

// ---------------- smem layout (bytes) ----------------
#define SM_BIAS 0
#define SM_AHI  512
#define SM_EPI  512
#define SM_BH   68608
#define SM_TOTAL 136192
#define ASTR 272     // A row stride bytes (136 f16)
#define BSTR 528     // B row stride bytes (264 f16)

// ---------------- conv phase (proven R16 body) ----------------
__device__ __noinline__ void conv_phase(
    char* sm, int tid, int bId,
    const uint32_t* __restrict__ mean16, const uint32_t* __restrict__ xin16,
    const float* __restrict__ Wl, const float* __restrict__ bl,
    const float* __restrict__ Wr, uint32_t* __restrict__ out16, int to_pool) {
    float* sBias = (float*)(sm + SM_BIAS);
    float* sEpi  = (float*)(sm + SM_EPI);
    int w = tid >> 5, lane = tid & 31;
    int quad = lane >> 2, tq = lane & 3;
    int rgrp = (w & 7) * 16;
    int cgrp = (w >> 3) * 32;

    if (tid < 128) sBias[tid] = bl[tid];

    for (int idx = tid; idx < 128 * 64; idx += THREADS) {
        int c = idx >> 6, p = idx & 63;
        float2 wl2 = ((const float2*)Wl)[idx];
        float2 wr2 = ((const float2*)Wr)[idx];
        *(uint32_t*)(sm + SM_BH + c * BSTR + 4 * p) = packf16(wl2.x, wl2.y);
        *(uint32_t*)(sm + SM_BH + c * BSTR + 256 + 4 * p) = packf16(wr2.x, wr2.y);
    }
    __syncthreads();

    const uint32_t smb = smem_u32(sm);
    int arow = (lane & 7) + ((lane >> 3) & 1) * 8;
    uint32_t aHi = smb + SM_AHI + (uint32_t)((rgrp + arow) * ASTR + (lane >> 4) * 16);
    int brow = (lane & 7) + ((lane >> 4) & 1) * 8;
    uint32_t bH = smb + SM_BH + (uint32_t)((cgrp + brow) * BSTR + ((lane >> 3) & 1) * 16);

    int sr[4], sq[4];
    #pragma unroll
    for (int j = 0; j < 4; j++) {
        int idx = tid + j * THREADS;
        sr[j] = idx >> 5; sq[j] = idx & 31;
    }

    uint2 pf[4];
    int tb = bId * 128;
    #pragma unroll
    for (int j = 0; j < 4; j++) {
        int grow = tb + sr[j];
        pf[j] = (grow < NN) ? ((const uint2*)mean16)[(long long)grow * 32 + sq[j]]
                            : make_uint2(0u, 0u);
    }

    for (int tile = bId; tile * 128 < NN; tile += GRID) {
        tb = tile * 128;
        float acc[4][4];
        #pragma unroll
        for (int nt = 0; nt < 4; nt++)
            #pragma unroll
            for (int j = 0; j < 4; j++) acc[nt][j] = 0.f;

        #pragma unroll
        for (int j = 0; j < 4; j++)
            *(uint2*)(sm + SM_AHI + sr[j] * ASTR + 8 * sq[j]) = pf[j];
        __syncthreads();

        #pragma unroll
        for (int j = 0; j < 4; j++) {
            int grow = tb + sr[j];
            pf[j] = (grow < NN) ? ((const uint2*)xin16)[(long long)grow * 32 + sq[j]]
                                : make_uint2(0u, 0u);
        }

        #pragma unroll
        for (int ks = 0; ks < 8; ks++) {
            uint32_t ah[4], bh0[4], bh1[4];
            ldsm4(ah, aHi + ks * 32);
            ldsm4(bh0, bH + ks * 32);
            ldsm4(bh1, bH + (uint32_t)(16 * BSTR) + ks * 32);
            mma16816(acc[0], ah, bh0[0], bh0[1]);
            mma16816(acc[1], ah, bh0[2], bh0[3]);
            mma16816(acc[2], ah, bh1[0], bh1[1]);
            mma16816(acc[3], ah, bh1[2], bh1[3]);
        }
        __syncthreads();

        #pragma unroll
        for (int j = 0; j < 4; j++)
            *(uint2*)(sm + SM_AHI + sr[j] * ASTR + 8 * sq[j]) = pf[j];
        __syncthreads();

        {
            int ntb = tb + GRID * 128;
            #pragma unroll
            for (int j = 0; j < 4; j++) {
                int grow = ntb + sr[j];
                pf[j] = (grow < NN)
                      ? ((const uint2*)mean16)[(long long)grow * 32 + sq[j]]
                      : make_uint2(0u, 0u);
            }
        }

        #pragma unroll
        for (int ks = 0; ks < 8; ks++) {
            uint32_t ah[4], bh0[4], bh1[4];
            ldsm4(ah, aHi + ks * 32);
            ldsm4(bh0, bH + 256u + ks * 32);
            ldsm4(bh1, bH + (uint32_t)(16 * BSTR) + 256u + ks * 32);
            mma16816(acc[0], ah, bh0[0], bh0[1]);
            mma16816(acc[1], ah, bh0[2], bh0[3]);
            mma16816(acc[2], ah, bh1[0], bh1[1]);
            mma16816(acc[3], ah, bh1[2], bh1[3]);
        }
        __syncthreads();

        #pragma unroll
        for (int nt = 0; nt < 4; nt++) {
            int r0 = rgrp + quad;
            int c = cgrp + nt * 8 + tq * 2;
            *(float2*)&sEpi[r0 * 132 + c] = make_float2(acc[nt][0], acc[nt][1]);
            *(float2*)&sEpi[(r0 + 8) * 132 + c] = make_float2(acc[nt][2], acc[nt][3]);
        }
        __syncthreads();
        for (int idx = tid; idx < 128 * 32; idx += THREADS) {
            int r = idx >> 5, q = idx & 31;
            int grow = tb + r;
            if (grow < NN) {
                float4 v = *(float4*)&sEpi[r * 132 + 4 * q];
                float4 b = *(float4*)&sBias[4 * q];
                v.x += b.x; v.y += b.y; v.z += b.z; v.w += b.w;
                if (to_pool) {
                    float* p = g_pool + (long long)g_bat[grow] * 128 + 4 * q;
                    asm volatile("red.global.add.v4.f32 [%0], {%1,%2,%3,%4};"
                                 :: "l"(p), "f"(v.x), "f"(v.y), "f"(v.z), "f"(v.w)
                                 : "memory");
                } else {
                    ((uint2*)out16)[(long long)grow * 32 + q] =
                        make_uint2(packf16(v.x, v.y), packf16(v.z, v.w));
                }
            }
        }
        __syncthreads();
    }
}

// ---------------- gather phase ----------------
__device__ __noinline__ void gather_phase(int tid, int bId,
                                          const uint32_t* __restrict__ feat16,
                                          uint32_t* __restrict__ agg16) {
    int lane = tid & 31;
    int warp = bId * 32 + (tid >> 5);
    for (int node = warp; node < NN; node += NWARP) {
        int beg = g_off[node], end = g_off[node + 1];
        float4 acc = make_float4(0.f, 0.f, 0.f, 0.f);
        int e = beg;
        for (; e + 7 < end; e += 8) {
            uint2 v[8];
            #pragma unroll
            for (int j = 0; j < 8; j++) {
                int sj = g_ssrc[e + j];
                v[j] = ((const uint2*)feat16)[(long long)sj * 32 + lane];
            }
            #pragma unroll
            for (int j = 0; j < 8; j++) h4acc(v[j], acc);
        }
        for (; e + 3 < end; e += 4) {
            uint2 v[4];
            #pragma unroll
            for (int j = 0; j < 4; j++) {
                int sj = g_ssrc[e + j];
                v[j] = ((const uint2*)feat16)[(long long)sj * 32 + lane];
            }
            #pragma unroll
            for (int j = 0; j < 4; j++) h4acc(v[j], acc);
        }
        for (; e < end; e++) {
            int s0 = g_ssrc[e];
            h4acc(((const uint2*)feat16)[(long long)s0 * 32 + lane], acc);
        }
        float inv = 1.f / (float)max(end - beg, 1);
        ((uint2*)agg16)[(long long)node * 32 + lane] =
            make_uint2(packf16(acc.x * inv, acc.y * inv),
                       packf16(acc.z * inv, acc.w * inv));
    }
}

// ---------------- the megakernel ----------------
__global__ void __launch_bounds__(THREADS, 1) mega_kernel(
    const float* __restrict__ x,
    const void* __restrict__ e_raw, const void* __restrict__ b_raw,
    const float* __restrict__ W1l, const float* __restrict__ b1,
    const float* __restrict__ W1r,
    const float* __restrict__ W2l, const float* __restrict__ b2,
    const float* __restrict__ W2r,
    const float* __restrict__ lin1w, const float* __restrict__ lin1b,
    const float* __restrict__ lin2w, const float* __restrict__ lin2b,
    const float* __restrict__ gamma, const float* __restrict__ beta,
    const float* __restrict__ rmean, const float* __restrict__ rvar,
    float* __restrict__ out) {
    extern __shared__ char sm[];
    int t = threadIdx.x, b = blockIdx.x;
    int gi = b * THREADS + t;
    const int gstride = GRID * THREADS;

    // ---- phase 0: zero deg/pool + dtype detect ----
    for (int j = gi; j < NN; j += gstride) g_deg[j] = 0;
    for (int j = gi; j < NG * 128; j += gstride) g_pool[j] = 0.f;
    if (gi < 4096) {
        if (((const unsigned long long*)e_raw)[gi] >= (1ull << 32))
            atomicExch(&g_eflag, 1);
        if (gi < 2048 && ((const unsigned long long*)b_raw)[gi] >= (1ull << 32))
            atomicExch(&g_bflag, 1);
    }
    gsync(t);

    // ---- phase 1: normalize indices + histogram + x -> fp16 ----
    {
        int eflag = g_eflag, bflag = g_bflag;
        for (int e = gi; e < NE; e += gstride) {
            int ss, dd;
            if (eflag) {
                ss = ((const int*)e_raw)[e];
                dd = ((const int*)e_raw)[NE + e];
            } else {
                ss = (int)((const long long*)e_raw)[e];
                dd = (int)((const long long*)e_raw)[NE + e];
            }
            g_src[e] = ss;
            g_dst[e] = dd;
            atomicAdd(&g_deg[dd], 1);
        }
        for (int n = gi; n < NN; n += gstride)
            g_bat[n] = bflag ? ((const int*)b_raw)[n]
                             : (int)((const long long*)b_raw)[n];
        for (int idx = gi; idx < NN * 64; idx += gstride) {
            float2 v = ((const float2*)x)[idx];
            g_x16[idx] = packf16(v.x, v.y);
        }
    }
    gsync(t);

    // ---- phase 2: block-local exclusive scan over 1024 degrees ----
    int loc;
    {
        int* s = (int*)sm;
        int d = (gi < NN) ? g_deg[gi] : 0;
        s[t] = d;
        __syncthreads();
        #pragma unroll
        for (int off = 1; off < THREADS; off <<= 1) {
            int v = (t >= off) ? s[t - off] : 0;
            __syncthreads();
            s[t] += v;
            __syncthreads();
        }
        loc = s[t] - d;
        if (t == THREADS - 1) g_bsum[b] = s[THREADS - 1];
    }
    gsync(t);

    // ---- phase 3: scan block sums, write offsets/cursors ----
    {
        int* bs = (int*)sm;
        int v = (t < GRID) ? g_bsum[t] : 0;
        if (t < 256) bs[t] = v;
        __syncthreads();
        #pragma unroll
        for (int off = 1; off < 256; off <<= 1) {
            int u = (t < 256 && t >= off) ? bs[t - off] : 0;
            __syncthreads();
            if (t < 256) bs[t] += u;
            __syncthreads();
        }
        int base = bs[b] - g_bsum[b];
        if (gi < NN) { int o = loc + base; g_off[gi] = o; g_cur[gi] = o; }
        if (gi == 0) g_off[NN] = NE;
    }
    gsync(t);

    // ---- phase 4: scatter src ids into CSR order ----
    for (int e = gi; e < NE; e += gstride) {
        int dd = g_dst[e];
        int pos = atomicAdd(&g_cur[dd], 1);
        g_ssrc[pos] = g_src[e];
    }
    gsync(t);

    // ---- phase 5: gather1 (x16 -> agg16) ----
    gather_phase(t, b, g_x16, g_agg16);
    gsync(t);

    // ---- phase 6: conv1 (agg16, x16 -> h116) ----
    conv_phase(sm, t, b, g_agg16, g_x16, W1l, b1, W1r, g_h116, 0);
    gsync(t);

    // ---- phase 7: gather2 (h116 -> agg16) ----
    gather_phase(t, b, g_h116, g_agg16);
    gsync(t);

    // ---- phase 8: conv2 (agg16, h116 -> pool) ----
    conv_phase(sm, t, b, g_agg16, g_h116, W2l, b2, W2r, nullptr, 1);
    gsync(t);

    // ---- phase 9: head (lin1 + BN + relu + lin2) ----
    {
        float* p = (float*)sm;
        float* h = (float*)(sm + 512);
        for (int g = b; g < NG; g += GRID) {
            if (t < 128) p[t] = g_pool[g * 128 + t];
            __syncthreads();
            if (t < 128) {
                float acc = lin1b[t];
                const float* wv = lin1w + t * 128;
                #pragma unroll 8
                for (int k = 0; k < 128; k++) acc += p[k] * wv[k];
                acc = (acc - rmean[t]) * rsqrtf(rvar[t] + 1e-5f) * gamma[t] + beta[t];
                h[t] = fmaxf(acc, 0.f);
            }
            __syncthreads();
            if (t < 64) {
                int wid = t >> 5, lane = t & 31;
                const float* w2 = lin2w + wid * 128;
                float s = 0.f;
                #pragma unroll
                for (int k = lane; k < 128; k += 32) s += h[k] * w2[k];
                #pragma unroll
                for (int o = 16; o; o >>= 1) s += __shfl_xor_sync(0xffffffffu, s, o);
                if (lane == 0) out[g * 2 + wid] = s + lin2b[wid];
            }
            __syncthreads();
        }
    }
}

// ---------------- launch ----------------
extern "C" void kernel_launch(void* const* d_in, const int* in_sizes, int n_in,
                              void* d_out, int out_size) {
    const float* x        = (const float*)d_in[0];
    const void*  ei_raw   = (const void*)d_in[1];
    const void*  bat_raw  = (const void*)d_in[2];
    const float* W1l      = (const float*)d_in[3];
    const float* b1       = (const float*)d_in[4];
    const float* W1r      = (const float*)d_in[5];
    const float* W2l      = (const float*)d_in[6];
    const float* b2       = (const float*)d_in[7];
    const float* W2r      = (const float*)d_in[8];
    const float* lin1w    = (const float*)d_in[9];
    const float* lin1b    = (const float*)d_in[10];
    const float* lin2w    = (const float*)d_in[11];
    const float* lin2b    = (const float*)d_in[12];
    const float* gamma    = (const float*)d_in[13];
    const float* beta     = (const float*)d_in[14];
    const float* rmean    = (const float*)d_in[15];
    const float* rvar     = (const float*)d_in[16];
    float* out            = (float*)d_out;

    cudaFuncSetAttribute(mega_kernel,
                         cudaFuncAttributeMaxDynamicSharedMemorySize, SM_TOTAL);

    mega_kernel<<<GRID, THREADS, SM_TOTAL>>>(
        x, ei_raw, bat_raw, W1l, b1, W1r, W2l, b2, W2r,
        lin1w, lin1b, lin2w, lin2b, gamma, beta, rmean, rvar, out);
}